// round 3
// baseline (speedup 1.0000x reference)
#include <cuda_runtime.h>
#include <cuda_bf16.h>
#include <stdint.h>

#define N_NODES 100000
#define N_EDGES 1600000
#define NUM_RELS 8
#define H_DIM 64
#define K_TOT 512             // NUM_RELS * H_DIM
#define NSEG (N_NODES * NUM_RELS)      // 800000 segments (dst*8+etype)
#define SCAN_BLOCKS ((NSEG + 1023) / 1024)   // 782
#define NLDA 72               // padded smem leading dim (bf16 elems)

// ---------------- scratch (static device allocations) ----------------
__device__ float g_x[(size_t)N_NODES * H_DIM];          // 25.6 MB
__device__ float g_h[(size_t)N_NODES * H_DIM];          // 25.6 MB
__device__ float g_A[(size_t)N_NODES * K_TOT];          // 204.8 MB (per-rel aggregates)
__device__ int   g_cnt[NSEG];
__device__ int   g_rowptr[NSEG + 1];
__device__ int   g_wp[NSEG];
__device__ int   g_bsum[1024];
__device__ int   g_esrc[N_EDGES];
__device__ float g_enorm[N_EDGES];
__device__ __nv_bfloat16 g_Wth[2 * H_DIM * K_TOT];      // Bt layout [layer][o][k] hi
__device__ __nv_bfloat16 g_Wtl[2 * H_DIM * K_TOT];      // lo

// ---------------- CSR build over (dst, rel) segments ----------------
__global__ void k_zero_cnt() {
    int i = blockIdx.x * blockDim.x + threadIdx.x;
    if (i < NSEG) g_cnt[i] = 0;
}

__global__ void k_hist(const int* __restrict__ dst, const int* __restrict__ etype) {
    int e = blockIdx.x * blockDim.x + threadIdx.x;
    if (e < N_EDGES) atomicAdd(&g_cnt[dst[e] * NUM_RELS + etype[e]], 1);
}

__global__ void k_scan_local() {   // 1024 threads/block
    __shared__ int warpsums[32];
    int i = blockIdx.x * 1024 + threadIdx.x;
    int v = (i < NSEG) ? g_cnt[i] : 0;
    int lane = threadIdx.x & 31, wid = threadIdx.x >> 5;
    int s = v;
    #pragma unroll
    for (int d = 1; d < 32; d <<= 1) {
        int t = __shfl_up_sync(0xFFFFFFFFu, s, d);
        if (lane >= d) s += t;
    }
    if (lane == 31) warpsums[wid] = s;
    __syncthreads();
    if (wid == 0) {
        int ws = warpsums[lane];
        #pragma unroll
        for (int d = 1; d < 32; d <<= 1) {
            int t = __shfl_up_sync(0xFFFFFFFFu, ws, d);
            if (lane >= d) ws += t;
        }
        warpsums[lane] = ws;
    }
    __syncthreads();
    int base = (wid > 0) ? warpsums[wid - 1] : 0;
    int incl = s + base;
    if (i < NSEG) g_rowptr[i] = incl - v;               // local exclusive
    if (threadIdx.x == 1023) g_bsum[blockIdx.x] = incl; // block total
}

__global__ void k_scan_bsums(int nb) {   // 1 block of 1024
    __shared__ int sh[1024];
    int t = threadIdx.x;
    int v = (t < nb) ? g_bsum[t] : 0;
    sh[t] = v;
    __syncthreads();
    for (int off = 1; off < 1024; off <<= 1) {
        int add = (t >= off) ? sh[t - off] : 0;
        __syncthreads();
        sh[t] += add;
        __syncthreads();
    }
    if (t < nb) g_bsum[t] = sh[t] - v;   // exclusive
}

__global__ void k_scan_add() {
    int i = blockIdx.x * 1024 + threadIdx.x;
    if (i < NSEG) {
        int val = g_rowptr[i] + g_bsum[blockIdx.x];
        g_rowptr[i] = val;
        g_wp[i] = val;
    }
    if (blockIdx.x == 0 && threadIdx.x == 0) g_rowptr[NSEG] = N_EDGES;
}

__global__ void k_scatter(const int* __restrict__ src, const int* __restrict__ dst,
                          const int* __restrict__ etype, const float* __restrict__ norm) {
    int e = blockIdx.x * blockDim.x + threadIdx.x;
    if (e >= N_EDGES) return;
    int seg = dst[e] * NUM_RELS + etype[e];
    int p = atomicAdd(&g_wp[seg], 1);
    g_esrc[p] = src[e];
    g_enorm[p] = norm[e];
}

// ---------------- weight prep: Wcat[r*64+k][o] = sum_b comp[r,b] V[b][k][o] --------
// stored transposed+split:  g_Wth[layer][o*512 + r*64+k]
__global__ void k_prepw(const float* __restrict__ V1, const float* __restrict__ c1,
                        const float* __restrict__ V2, const float* __restrict__ c2) {
    int t = blockIdx.x * blockDim.x + threadIdx.x;
    if (t >= 2 * H_DIM * K_TOT) return;
    int sel = t >= H_DIM * K_TOT;
    int u = t & (H_DIM * K_TOT - 1);
    int o = u >> 9;          // 0..63
    int c = u & 511;         // r*64+k
    int r = c >> 6, k = c & 63;
    const float* V = sel ? V2 : V1;
    const float* cp = sel ? c2 : c1;
    float s = 0.f;
    #pragma unroll
    for (int b = 0; b < 8; b++)
        s += cp[r * 8 + b] * V[(b * 64 + k) * 64 + o];
    __nv_bfloat16 hi = __float2bfloat16(s);
    __nv_bfloat16 lo = __float2bfloat16(s - __bfloat162float(hi));
    g_Wth[t] = hi;
    g_Wtl[t] = lo;
}

// ---------------- mma helper ----------------
__device__ __forceinline__ void mma16816(float* c, const uint32_t* a, const uint32_t* b) {
    asm volatile(
        "mma.sync.aligned.m16n8k16.row.col.f32.bf16.bf16.f32 "
        "{%0,%1,%2,%3}, {%4,%5,%6,%7}, {%8,%9}, {%0,%1,%2,%3};\n"
        : "+f"(c[0]), "+f"(c[1]), "+f"(c[2]), "+f"(c[3])
        : "r"(a[0]), "r"(a[1]), "r"(a[2]), "r"(a[3]), "r"(b[0]), "r"(b[1]));
}

__device__ __forceinline__ void split_bf16(float v, __nv_bfloat16& hi, __nv_bfloat16& lo) {
    hi = __float2bfloat16(v);
    lo = __float2bfloat16(v - __bfloat162float(hi));
}

// ---------------- size matcher: g_x = gather(emb)[N,256] @ sm_w^T + sm_b -----------
__global__ void k_sm(const int* __restrict__ feat, const float* __restrict__ emb,
                     const float* __restrict__ smw, const float* __restrict__ smb) {
    extern __shared__ char smraw[];
    __nv_bfloat16* Ahi = (__nv_bfloat16*)smraw;                 // 128*72
    __nv_bfloat16* Alo = Ahi + 128 * NLDA;
    __nv_bfloat16* Bhi = Alo + 128 * NLDA;                      // 64*72
    __nv_bfloat16* Blo = Bhi + 64 * NLDA;
    int* sfeat = (int*)(Blo + 64 * NLDA);                       // 128*8

    int tid = threadIdx.x;
    int rb = blockIdx.x * 128;

    for (int idx = tid; idx < 128 * 8; idx += 256) {
        int r = idx >> 3, j = idx & 7;
        sfeat[idx] = (rb + r < N_NODES) ? feat[(size_t)(rb + r) * 8 + j] : 0;
    }

    int lane = tid & 31, warp = tid >> 5;
    int wr = (warp >> 2) * 64;       // 0 or 64
    int wc = (warp & 3) * 16;        // 0,16,32,48
    int g = lane >> 2, t = lane & 3;

    float C[8][4];
    #pragma unroll
    for (int i = 0; i < 8; i++)
        #pragma unroll
        for (int j = 0; j < 4; j++) C[i][j] = 0.f;

    for (int kc = 0; kc < 4; kc++) {
        __syncthreads();
        for (int idx = tid; idx < 128 * 64; idx += 256) {
            int r = idx >> 6, k = idx & 63;
            float v = 0.f;
            if (rb + r < N_NODES) {
                int fid = sfeat[r * 8 + kc * 2 + (k >> 5)];
                v = emb[(size_t)fid * 32 + (k & 31)];
            }
            __nv_bfloat16 h, l; split_bf16(v, h, l);
            Ahi[r * NLDA + k] = h; Alo[r * NLDA + k] = l;
        }
        for (int idx = tid; idx < 64 * 64; idx += 256) {
            int n = idx >> 6, k = idx & 63;
            float v = smw[n * 256 + kc * 64 + k];
            __nv_bfloat16 h, l; split_bf16(v, h, l);
            Bhi[n * NLDA + k] = h; Blo[n * NLDA + k] = l;
        }
        __syncthreads();

        #pragma unroll
        for (int ks = 0; ks < 4; ks++) {
            int k0 = ks * 16;
            #pragma unroll
            for (int p = 0; p < 3; p++) {
                const __nv_bfloat16* As = (p == 1) ? Alo : Ahi;
                const __nv_bfloat16* Bs = (p == 2) ? Blo : Bhi;
                uint32_t a[4][4], b[2][2];
                #pragma unroll
                for (int mt = 0; mt < 4; mt++) {
                    int r0 = wr + mt * 16;
                    a[mt][0] = *(const uint32_t*)(As + (r0 + g) * NLDA + k0 + 2 * t);
                    a[mt][1] = *(const uint32_t*)(As + (r0 + g + 8) * NLDA + k0 + 2 * t);
                    a[mt][2] = *(const uint32_t*)(As + (r0 + g) * NLDA + k0 + 8 + 2 * t);
                    a[mt][3] = *(const uint32_t*)(As + (r0 + g + 8) * NLDA + k0 + 8 + 2 * t);
                }
                #pragma unroll
                for (int nt = 0; nt < 2; nt++) {
                    int c0 = wc + nt * 8 + g;
                    b[nt][0] = *(const uint32_t*)(Bs + c0 * NLDA + k0 + 2 * t);
                    b[nt][1] = *(const uint32_t*)(Bs + c0 * NLDA + k0 + 8 + 2 * t);
                }
                #pragma unroll
                for (int mt = 0; mt < 4; mt++)
                    #pragma unroll
                    for (int nt = 0; nt < 2; nt++)
                        mma16816(C[mt * 2 + nt], a[mt], b[nt]);
            }
        }
    }

    #pragma unroll
    for (int mt = 0; mt < 4; mt++) {
        int r0 = rb + wr + mt * 16 + g;
        int r1 = r0 + 8;
        #pragma unroll
        for (int nt = 0; nt < 2; nt++) {
            int gc = wc + nt * 8 + 2 * t;
            float b0 = smb[gc], b1 = smb[gc + 1];
            if (r0 < N_NODES)
                *(float2*)(g_x + (size_t)r0 * 64 + gc) =
                    make_float2(C[mt * 2 + nt][0] + b0, C[mt * 2 + nt][1] + b1);
            if (r1 < N_NODES)
                *(float2*)(g_x + (size_t)r1 * 64 + gc) =
                    make_float2(C[mt * 2 + nt][2] + b0, C[mt * 2 + nt][3] + b1);
        }
    }
}

// ---------------- edge aggregation into A: warp per node --------------------------
// A[n][r*64+c] = sum_{e in seg(n,r)} norm_e * X[src_e][c]
__global__ void k_agg(int phase) {
    const float* __restrict__ X = phase ? g_h : g_x;
    int node = blockIdx.x * 8 + (threadIdx.x >> 5);
    int lane = threadIdx.x & 31;
    if (node >= N_NODES) return;
    int c = lane * 2;

    float2 acc[NUM_RELS];
    #pragma unroll
    for (int r = 0; r < NUM_RELS; r++) acc[r] = make_float2(0.f, 0.f);

    #pragma unroll
    for (int r = 0; r < NUM_RELS; r++) {
        int seg = node * NUM_RELS + r;
        int e = g_rowptr[seg], end = g_rowptr[seg + 1];
        for (; e + 4 <= end; e += 4) {
            int s0 = g_esrc[e],     s1 = g_esrc[e + 1];
            int s2 = g_esrc[e + 2], s3 = g_esrc[e + 3];
            float n0 = g_enorm[e],     n1 = g_enorm[e + 1];
            float n2 = g_enorm[e + 2], n3 = g_enorm[e + 3];
            float2 v0 = *(const float2*)(X + (size_t)s0 * 64 + c);
            float2 v1 = *(const float2*)(X + (size_t)s1 * 64 + c);
            float2 v2 = *(const float2*)(X + (size_t)s2 * 64 + c);
            float2 v3 = *(const float2*)(X + (size_t)s3 * 64 + c);
            acc[r].x = fmaf(n0, v0.x, acc[r].x); acc[r].y = fmaf(n0, v0.y, acc[r].y);
            acc[r].x = fmaf(n1, v1.x, acc[r].x); acc[r].y = fmaf(n1, v1.y, acc[r].y);
            acc[r].x = fmaf(n2, v2.x, acc[r].x); acc[r].y = fmaf(n2, v2.y, acc[r].y);
            acc[r].x = fmaf(n3, v3.x, acc[r].x); acc[r].y = fmaf(n3, v3.y, acc[r].y);
        }
        for (; e < end; e++) {
            int s0 = g_esrc[e];
            float n0 = g_enorm[e];
            float2 v0 = *(const float2*)(X + (size_t)s0 * 64 + c);
            acc[r].x = fmaf(n0, v0.x, acc[r].x); acc[r].y = fmaf(n0, v0.y, acc[r].y);
        }
    }

    float* dstp = g_A + (size_t)node * K_TOT + c;
    #pragma unroll
    for (int r = 0; r < NUM_RELS; r++)
        __stcs((float2*)(dstp + r * 64), acc[r]);
}

// ---------------- output GEMM: out[n][o] = A[n,:512] @ Wcat[:,o] + bias ------------
// block: 128 rows x 64 cols, K=512 in 8 chunks of 64. 256 threads (8 warps 2x4).
__global__ void k_out(int phase, const float* __restrict__ bias, float* __restrict__ dout) {
    float* __restrict__ OP = phase ? dout : g_h;
    const __nv_bfloat16* __restrict__ Wh = g_Wth + phase * H_DIM * K_TOT;
    const __nv_bfloat16* __restrict__ Wl = g_Wtl + phase * H_DIM * K_TOT;

    extern __shared__ char smraw[];
    __nv_bfloat16* Ahi = (__nv_bfloat16*)smraw;     // 128*72
    __nv_bfloat16* Alo = Ahi + 128 * NLDA;
    __nv_bfloat16* Bhi = Alo + 128 * NLDA;          // 64*72
    __nv_bfloat16* Blo = Bhi + 64 * NLDA;

    int tid = threadIdx.x;
    int rb = blockIdx.x * 128;

    int lane = tid & 31, warp = tid >> 5;
    int wr = (warp >> 2) * 64;
    int wc = (warp & 3) * 16;
    int g = lane >> 2, t = lane & 3;

    float C[8][4];
    #pragma unroll
    for (int i = 0; i < 8; i++)
        #pragma unroll
        for (int j = 0; j < 4; j++) C[i][j] = 0.f;

    for (int kc = 0; kc < 8; kc++) {
        __syncthreads();
        for (int idx = tid; idx < 128 * 64; idx += 256) {
            int r = idx >> 6, k = idx & 63;
            float v = 0.f;
            if (rb + r < N_NODES)
                v = __ldcs(g_A + (size_t)(rb + r) * K_TOT + kc * 64 + k);
            __nv_bfloat16 h, l; split_bf16(v, h, l);
            Ahi[r * NLDA + k] = h; Alo[r * NLDA + k] = l;
        }
        for (int idx = tid; idx < 64 * 64; idx += 256) {
            int n = idx >> 6, k = idx & 63;
            Bhi[n * NLDA + k] = Wh[n * K_TOT + kc * 64 + k];
            Blo[n * NLDA + k] = Wl[n * K_TOT + kc * 64 + k];
        }
        __syncthreads();

        #pragma unroll
        for (int ks = 0; ks < 4; ks++) {
            int k0 = ks * 16;
            #pragma unroll
            for (int p = 0; p < 3; p++) {
                const __nv_bfloat16* As = (p == 1) ? Alo : Ahi;
                const __nv_bfloat16* Bs = (p == 2) ? Blo : Bhi;
                uint32_t a[4][4], b[2][2];
                #pragma unroll
                for (int mt = 0; mt < 4; mt++) {
                    int r0 = wr + mt * 16;
                    a[mt][0] = *(const uint32_t*)(As + (r0 + g) * NLDA + k0 + 2 * t);
                    a[mt][1] = *(const uint32_t*)(As + (r0 + g + 8) * NLDA + k0 + 2 * t);
                    a[mt][2] = *(const uint32_t*)(As + (r0 + g) * NLDA + k0 + 8 + 2 * t);
                    a[mt][3] = *(const uint32_t*)(As + (r0 + g + 8) * NLDA + k0 + 8 + 2 * t);
                }
                #pragma unroll
                for (int nt = 0; nt < 2; nt++) {
                    int c0 = wc + nt * 8 + g;
                    b[nt][0] = *(const uint32_t*)(Bs + c0 * NLDA + k0 + 2 * t);
                    b[nt][1] = *(const uint32_t*)(Bs + c0 * NLDA + k0 + 8 + 2 * t);
                }
                #pragma unroll
                for (int mt = 0; mt < 4; mt++)
                    #pragma unroll
                    for (int nt = 0; nt < 2; nt++)
                        mma16816(C[mt * 2 + nt], a[mt], b[nt]);
            }
        }
    }

    int dorelu = (phase == 0);
    #pragma unroll
    for (int mt = 0; mt < 4; mt++) {
        int r0 = rb + wr + mt * 16 + g;
        int r1 = r0 + 8;
        #pragma unroll
        for (int nt = 0; nt < 2; nt++) {
            int gc = wc + nt * 8 + 2 * t;
            float b0 = bias[gc], b1 = bias[gc + 1];
            float c00 = C[mt * 2 + nt][0] + b0, c01 = C[mt * 2 + nt][1] + b1;
            float c10 = C[mt * 2 + nt][2] + b0, c11 = C[mt * 2 + nt][3] + b1;
            if (dorelu) {
                c00 = fmaxf(c00, 0.f); c01 = fmaxf(c01, 0.f);
                c10 = fmaxf(c10, 0.f); c11 = fmaxf(c11, 0.f);
            }
            if (r0 < N_NODES)
                *(float2*)(OP + (size_t)r0 * 64 + gc) = make_float2(c00, c01);
            if (r1 < N_NODES)
                *(float2*)(OP + (size_t)r1 * 64 + gc) = make_float2(c10, c11);
        }
    }
}

// ---------------- launch ----------------
extern "C" void kernel_launch(void* const* d_in, const int* in_sizes, int n_in,
                              void* d_out, int out_size) {
    const int* feat = (const int*)d_in[0];
    const int* src = (const int*)d_in[1];
    const int* dst = (const int*)d_in[2];
    const int* etype = (const int*)d_in[3];
    const float* norm = (const float*)d_in[4];
    const float* emb = (const float*)d_in[5];
    const float* smw = (const float*)d_in[6];
    const float* smb = (const float*)d_in[7];
    const float* V1 = (const float*)d_in[8];
    const float* c1 = (const float*)d_in[9];
    const float* b1 = (const float*)d_in[10];
    const float* V2 = (const float*)d_in[11];
    const float* c2 = (const float*)d_in[12];
    const float* b2 = (const float*)d_in[13];
    float* out = (float*)d_out;

    const int smemSM = (128 * NLDA * 2 + 64 * NLDA * 2) * 2 + 128 * 8 * 4;
    const int smemOUT = (128 * NLDA * 2 + 64 * NLDA * 2) * 2;
    static int attr_done = 0;
    if (!attr_done) {
        cudaFuncSetAttribute(k_sm, cudaFuncAttributeMaxDynamicSharedMemorySize, smemSM);
        cudaFuncSetAttribute(k_out, cudaFuncAttributeMaxDynamicSharedMemorySize, smemOUT);
        attr_done = 1;
    }

    // CSR build over (dst, rel) segments
    k_zero_cnt<<<(NSEG + 255) / 256, 256>>>();
    k_hist<<<N_EDGES / 256, 256>>>(dst, etype);
    k_scan_local<<<SCAN_BLOCKS, 1024>>>();
    k_scan_bsums<<<1, 1024>>>(SCAN_BLOCKS);
    k_scan_add<<<SCAN_BLOCKS, 1024>>>();
    k_scatter<<<N_EDGES / 256, 256>>>(src, dst, etype, norm);

    // weights (bf16 hi/lo, transposed)
    k_prepw<<<(2 * H_DIM * K_TOT) / 256, 256>>>(V1, c1, V2, c2);

    // size matcher -> g_x
    k_sm<<<(N_NODES + 127) / 128, 256, smemSM>>>(feat, emb, smw, smb);

    // layer 1: aggregate x -> A, then transform A -> g_h (relu)
    k_agg<<<(N_NODES + 7) / 8, 256>>>(0);
    k_out<<<(N_NODES + 127) / 128, 256, smemOUT>>>(0, b1, nullptr);

    // layer 2: aggregate h -> A, then transform A -> out
    k_agg<<<(N_NODES + 7) / 8, 256>>>(1);
    k_out<<<(N_NODES + 127) / 128, 256, smemOUT>>>(1, b2, out);
}

// round 4
// speedup vs baseline: 1.3067x; 1.3067x over previous
#include <cuda_runtime.h>
#include <cuda_bf16.h>
#include <stdint.h>

#define N_NODES 100000
#define N_EDGES 1600000
#define NUM_RELS 8
#define H_DIM 64
#define K_TOT 512             // NUM_RELS * H_DIM
#define NSEG (N_NODES * NUM_RELS)      // 800000 segments (dst*8+etype)
#define SCAN_BLOCKS ((NSEG + 1023) / 1024)   // 782
#define NLDA 72               // padded smem leading dim (bf16 elems)

// ---------------- scratch (static device allocations) ----------------
__device__ float g_x[(size_t)N_NODES * H_DIM];          // 25.6 MB
__device__ float g_h[(size_t)N_NODES * H_DIM];          // 25.6 MB
__device__ int   g_cnt[NSEG];
__device__ int   g_rowptr[NSEG + 1];
__device__ int   g_wp[NSEG];
__device__ int   g_bsum[1024];
__device__ int   g_esrc[N_EDGES];
__device__ float g_enorm[N_EDGES];
__device__ __nv_bfloat16 g_Wth[2 * H_DIM * K_TOT];      // Bt layout [layer][o*512 + r*64+k] hi
__device__ __nv_bfloat16 g_Wtl[2 * H_DIM * K_TOT];      // lo

// ---------------- CSR build over (dst, rel) segments ----------------
__global__ void k_zero_cnt() {
    int i = blockIdx.x * blockDim.x + threadIdx.x;
    if (i < NSEG) g_cnt[i] = 0;
}

__global__ void k_hist(const int* __restrict__ dst, const int* __restrict__ etype) {
    int e = blockIdx.x * blockDim.x + threadIdx.x;
    if (e < N_EDGES) atomicAdd(&g_cnt[dst[e] * NUM_RELS + etype[e]], 1);
}

__global__ void k_scan_local() {   // 1024 threads/block
    __shared__ int warpsums[32];
    int i = blockIdx.x * 1024 + threadIdx.x;
    int v = (i < NSEG) ? g_cnt[i] : 0;
    int lane = threadIdx.x & 31, wid = threadIdx.x >> 5;
    int s = v;
    #pragma unroll
    for (int d = 1; d < 32; d <<= 1) {
        int t = __shfl_up_sync(0xFFFFFFFFu, s, d);
        if (lane >= d) s += t;
    }
    if (lane == 31) warpsums[wid] = s;
    __syncthreads();
    if (wid == 0) {
        int ws = warpsums[lane];
        #pragma unroll
        for (int d = 1; d < 32; d <<= 1) {
            int t = __shfl_up_sync(0xFFFFFFFFu, ws, d);
            if (lane >= d) ws += t;
        }
        warpsums[lane] = ws;
    }
    __syncthreads();
    int base = (wid > 0) ? warpsums[wid - 1] : 0;
    int incl = s + base;
    if (i < NSEG) g_rowptr[i] = incl - v;               // local exclusive
    if (threadIdx.x == 1023) g_bsum[blockIdx.x] = incl; // block total
}

__global__ void k_scan_bsums(int nb) {   // 1 block of 1024
    __shared__ int sh[1024];
    int t = threadIdx.x;
    int v = (t < nb) ? g_bsum[t] : 0;
    sh[t] = v;
    __syncthreads();
    for (int off = 1; off < 1024; off <<= 1) {
        int add = (t >= off) ? sh[t - off] : 0;
        __syncthreads();
        sh[t] += add;
        __syncthreads();
    }
    if (t < nb) g_bsum[t] = sh[t] - v;   // exclusive
}

__global__ void k_scan_add() {
    int i = blockIdx.x * 1024 + threadIdx.x;
    if (i < NSEG) {
        int val = g_rowptr[i] + g_bsum[blockIdx.x];
        g_rowptr[i] = val;
        g_wp[i] = val;
    }
    if (blockIdx.x == 0 && threadIdx.x == 0) g_rowptr[NSEG] = N_EDGES;
}

__global__ void k_scatter(const int* __restrict__ src, const int* __restrict__ dst,
                          const int* __restrict__ etype, const float* __restrict__ norm) {
    int e = blockIdx.x * blockDim.x + threadIdx.x;
    if (e >= N_EDGES) return;
    int seg = dst[e] * NUM_RELS + etype[e];
    int p = atomicAdd(&g_wp[seg], 1);
    g_esrc[p] = src[e];
    g_enorm[p] = norm[e];
}

// ---------------- weight prep: Wcat[r*64+k][o] = sum_b comp[r,b] V[b][k][o] --------
// stored transposed+split:  g_Wth[layer][o*512 + r*64+k]
__global__ void k_prepw(const float* __restrict__ V1, const float* __restrict__ c1,
                        const float* __restrict__ V2, const float* __restrict__ c2) {
    int t = blockIdx.x * blockDim.x + threadIdx.x;
    if (t >= 2 * H_DIM * K_TOT) return;
    int sel = t >= H_DIM * K_TOT;
    int u = t & (H_DIM * K_TOT - 1);
    int o = u >> 9;          // 0..63
    int c = u & 511;         // r*64+k
    int r = c >> 6, k = c & 63;
    const float* V = sel ? V2 : V1;
    const float* cp = sel ? c2 : c1;
    float s = 0.f;
    #pragma unroll
    for (int b = 0; b < 8; b++)
        s += cp[r * 8 + b] * V[(b * 64 + k) * 64 + o];
    __nv_bfloat16 hi = __float2bfloat16(s);
    __nv_bfloat16 lo = __float2bfloat16(s - __bfloat162float(hi));
    g_Wth[t] = hi;
    g_Wtl[t] = lo;
}

// ---------------- mma helper ----------------
__device__ __forceinline__ void mma16816(float* c, const uint32_t* a, const uint32_t* b) {
    asm volatile(
        "mma.sync.aligned.m16n8k16.row.col.f32.bf16.bf16.f32 "
        "{%0,%1,%2,%3}, {%4,%5,%6,%7}, {%8,%9}, {%0,%1,%2,%3};\n"
        : "+f"(c[0]), "+f"(c[1]), "+f"(c[2]), "+f"(c[3])
        : "r"(a[0]), "r"(a[1]), "r"(a[2]), "r"(a[3]), "r"(b[0]), "r"(b[1]));
}

__device__ __forceinline__ void split_bf16(float v, __nv_bfloat16& hi, __nv_bfloat16& lo) {
    hi = __float2bfloat16(v);
    lo = __float2bfloat16(v - __bfloat162float(hi));
}

// ---------------- size matcher: g_x = gather(emb)[N,256] @ sm_w^T + sm_b -----------
__global__ void k_sm(const int* __restrict__ feat, const float* __restrict__ emb,
                     const float* __restrict__ smw, const float* __restrict__ smb) {
    extern __shared__ char smraw[];
    __nv_bfloat16* Ahi = (__nv_bfloat16*)smraw;                 // 128*72
    __nv_bfloat16* Alo = Ahi + 128 * NLDA;
    __nv_bfloat16* Bhi = Alo + 128 * NLDA;                      // 64*72
    __nv_bfloat16* Blo = Bhi + 64 * NLDA;
    int* sfeat = (int*)(Blo + 64 * NLDA);                       // 128*8

    int tid = threadIdx.x;
    int rb = blockIdx.x * 128;

    for (int idx = tid; idx < 128 * 8; idx += 256) {
        int r = idx >> 3, j = idx & 7;
        sfeat[idx] = (rb + r < N_NODES) ? feat[(size_t)(rb + r) * 8 + j] : 0;
    }

    int lane = tid & 31, warp = tid >> 5;
    int wr = (warp >> 2) * 64;       // 0 or 64
    int wc = (warp & 3) * 16;        // 0,16,32,48
    int g = lane >> 2, t = lane & 3;

    float C[8][4];
    #pragma unroll
    for (int i = 0; i < 8; i++)
        #pragma unroll
        for (int j = 0; j < 4; j++) C[i][j] = 0.f;

    for (int kc = 0; kc < 4; kc++) {
        __syncthreads();
        for (int idx = tid; idx < 128 * 64; idx += 256) {
            int r = idx >> 6, k = idx & 63;
            float v = 0.f;
            if (rb + r < N_NODES) {
                int fid = sfeat[r * 8 + kc * 2 + (k >> 5)];
                v = emb[(size_t)fid * 32 + (k & 31)];
            }
            __nv_bfloat16 h, l; split_bf16(v, h, l);
            Ahi[r * NLDA + k] = h; Alo[r * NLDA + k] = l;
        }
        for (int idx = tid; idx < 64 * 64; idx += 256) {
            int n = idx >> 6, k = idx & 63;
            float v = smw[n * 256 + kc * 64 + k];
            __nv_bfloat16 h, l; split_bf16(v, h, l);
            Bhi[n * NLDA + k] = h; Blo[n * NLDA + k] = l;
        }
        __syncthreads();

        #pragma unroll
        for (int ks = 0; ks < 4; ks++) {
            int k0 = ks * 16;
            #pragma unroll
            for (int p = 0; p < 3; p++) {
                const __nv_bfloat16* As = (p == 1) ? Alo : Ahi;
                const __nv_bfloat16* Bs = (p == 2) ? Blo : Bhi;
                uint32_t a[4][4], b[2][2];
                #pragma unroll
                for (int mt = 0; mt < 4; mt++) {
                    int r0 = wr + mt * 16;
                    a[mt][0] = *(const uint32_t*)(As + (r0 + g) * NLDA + k0 + 2 * t);
                    a[mt][1] = *(const uint32_t*)(As + (r0 + g + 8) * NLDA + k0 + 2 * t);
                    a[mt][2] = *(const uint32_t*)(As + (r0 + g) * NLDA + k0 + 8 + 2 * t);
                    a[mt][3] = *(const uint32_t*)(As + (r0 + g + 8) * NLDA + k0 + 8 + 2 * t);
                }
                #pragma unroll
                for (int nt = 0; nt < 2; nt++) {
                    int c0 = wc + nt * 8 + g;
                    b[nt][0] = *(const uint32_t*)(Bs + c0 * NLDA + k0 + 2 * t);
                    b[nt][1] = *(const uint32_t*)(Bs + c0 * NLDA + k0 + 8 + 2 * t);
                }
                #pragma unroll
                for (int mt = 0; mt < 4; mt++)
                    #pragma unroll
                    for (int nt = 0; nt < 2; nt++)
                        mma16816(C[mt * 2 + nt], a[mt], b[nt]);
            }
        }
    }

    #pragma unroll
    for (int mt = 0; mt < 4; mt++) {
        int r0 = rb + wr + mt * 16 + g;
        int r1 = r0 + 8;
        #pragma unroll
        for (int nt = 0; nt < 2; nt++) {
            int gc = wc + nt * 8 + 2 * t;
            float b0 = smb[gc], b1 = smb[gc + 1];
            if (r0 < N_NODES)
                *(float2*)(g_x + (size_t)r0 * 64 + gc) =
                    make_float2(C[mt * 2 + nt][0] + b0, C[mt * 2 + nt][1] + b1);
            if (r1 < N_NODES)
                *(float2*)(g_x + (size_t)r1 * 64 + gc) =
                    make_float2(C[mt * 2 + nt][2] + b0, C[mt * 2 + nt][3] + b1);
        }
    }
}

// ---------------- fused layer: aggregate per relation chunk in smem, then MMA ------
// out[n][o] = sum_r (sum_{e in seg(n,r)} norm_e X[src_e][:]) @ W[r-chunk][:,o] + bias
// block = 128 nodes; 8 warps. Warp w aggregates rows w*16..w*16+15 of the chunk.
__global__ void k_fused(int phase, const float* __restrict__ bias, float* __restrict__ dout) {
    const float* __restrict__ X = phase ? g_h : g_x;
    float* __restrict__ OP = phase ? dout : g_h;
    const __nv_bfloat16* __restrict__ Wh = g_Wth + phase * H_DIM * K_TOT;
    const __nv_bfloat16* __restrict__ Wl = g_Wtl + phase * H_DIM * K_TOT;

    extern __shared__ char smraw[];
    __nv_bfloat16* Ahi = (__nv_bfloat16*)smraw;     // 128*72
    __nv_bfloat16* Alo = Ahi + 128 * NLDA;
    __nv_bfloat16* Bhi = Alo + 128 * NLDA;          // 64*72
    __nv_bfloat16* Blo = Bhi + 64 * NLDA;

    int tid = threadIdx.x;
    int rb = blockIdx.x * 128;
    int lane = tid & 31, warp = tid >> 5;
    int c = lane * 2;                 // this lane's column pair during aggregation

    int wr = (warp >> 2) * 64;        // MMA row group
    int wc = (warp & 3) * 16;         // MMA col group
    int g = lane >> 2, t = lane & 3;

    float C[8][4];
    #pragma unroll
    for (int i = 0; i < 8; i++)
        #pragma unroll
        for (int j = 0; j < 4; j++) C[i][j] = 0.f;

    for (int r = 0; r < NUM_RELS; r++) {
        __syncthreads();   // previous chunk's MMA reads done

        // --- prefetch this warp's 16 rowptr pairs (lanes 0-15: beg, 16-31: end) ---
        int nd = rb + warp * 16 + (lane & 15);
        int rp = 0;
        if (nd < N_NODES)
            rp = g_rowptr[nd * NUM_RELS + r + ((lane >= 16) ? 1 : 0)];

        // --- aggregate 16 nodes into smem chunk rows ---
        #pragma unroll 1
        for (int i = 0; i < 16; i++) {
            int e   = __shfl_sync(0xFFFFFFFFu, rp, i);
            int end = __shfl_sync(0xFFFFFFFFu, rp, i + 16);
            float ax = 0.f, ay = 0.f;
            for (; e + 4 <= end; e += 4) {
                int s0 = g_esrc[e],     s1 = g_esrc[e + 1];
                int s2 = g_esrc[e + 2], s3 = g_esrc[e + 3];
                float n0 = g_enorm[e],     n1 = g_enorm[e + 1];
                float n2 = g_enorm[e + 2], n3 = g_enorm[e + 3];
                float2 v0 = *(const float2*)(X + (size_t)s0 * 64 + c);
                float2 v1 = *(const float2*)(X + (size_t)s1 * 64 + c);
                float2 v2 = *(const float2*)(X + (size_t)s2 * 64 + c);
                float2 v3 = *(const float2*)(X + (size_t)s3 * 64 + c);
                ax = fmaf(n0, v0.x, ax); ay = fmaf(n0, v0.y, ay);
                ax = fmaf(n1, v1.x, ax); ay = fmaf(n1, v1.y, ay);
                ax = fmaf(n2, v2.x, ax); ay = fmaf(n2, v2.y, ay);
                ax = fmaf(n3, v3.x, ax); ay = fmaf(n3, v3.y, ay);
            }
            for (; e < end; e++) {
                int s0 = g_esrc[e];
                float n0 = g_enorm[e];
                float2 v0 = *(const float2*)(X + (size_t)s0 * 64 + c);
                ax = fmaf(n0, v0.x, ax); ay = fmaf(n0, v0.y, ay);
            }
            int row = warp * 16 + i;
            __nv_bfloat16 h0, l0, h1, l1;
            split_bf16(ax, h0, l0);
            split_bf16(ay, h1, l1);
            __nv_bfloat162 ph; ph.x = h0; ph.y = h1;
            __nv_bfloat162 pl; pl.x = l0; pl.y = l1;
            *(__nv_bfloat162*)(Ahi + row * NLDA + c) = ph;
            *(__nv_bfloat162*)(Alo + row * NLDA + c) = pl;
        }

        // --- load B chunk (W rows for this relation), L2-resident ---
        for (int idx = tid; idx < 64 * 64; idx += 256) {
            int n = idx >> 6, k = idx & 63;
            Bhi[n * NLDA + k] = Wh[n * K_TOT + r * 64 + k];
            Blo[n * NLDA + k] = Wl[n * K_TOT + r * 64 + k];
        }
        __syncthreads();

        // --- 3-pass MMA over this 64-wide K chunk ---
        #pragma unroll
        for (int ks = 0; ks < 4; ks++) {
            int k0 = ks * 16;
            #pragma unroll
            for (int p = 0; p < 3; p++) {
                const __nv_bfloat16* As = (p == 1) ? Alo : Ahi;
                const __nv_bfloat16* Bs = (p == 2) ? Blo : Bhi;
                uint32_t a[4][4], b[2][2];
                #pragma unroll
                for (int mt = 0; mt < 4; mt++) {
                    int r0 = wr + mt * 16;
                    a[mt][0] = *(const uint32_t*)(As + (r0 + g) * NLDA + k0 + 2 * t);
                    a[mt][1] = *(const uint32_t*)(As + (r0 + g + 8) * NLDA + k0 + 2 * t);
                    a[mt][2] = *(const uint32_t*)(As + (r0 + g) * NLDA + k0 + 8 + 2 * t);
                    a[mt][3] = *(const uint32_t*)(As + (r0 + g + 8) * NLDA + k0 + 8 + 2 * t);
                }
                #pragma unroll
                for (int nt = 0; nt < 2; nt++) {
                    int c0 = wc + nt * 8 + g;
                    b[nt][0] = *(const uint32_t*)(Bs + c0 * NLDA + k0 + 2 * t);
                    b[nt][1] = *(const uint32_t*)(Bs + c0 * NLDA + k0 + 8 + 2 * t);
                }
                #pragma unroll
                for (int mt = 0; mt < 4; mt++)
                    #pragma unroll
                    for (int nt = 0; nt < 2; nt++)
                        mma16816(C[mt * 2 + nt], a[mt], b[nt]);
            }
        }
    }

    // --- epilogue: bias (+relu for layer 1) ---
    int dorelu = (phase == 0);
    #pragma unroll
    for (int mt = 0; mt < 4; mt++) {
        int r0 = rb + wr + mt * 16 + g;
        int r1 = r0 + 8;
        #pragma unroll
        for (int nt = 0; nt < 2; nt++) {
            int gc = wc + nt * 8 + 2 * t;
            float b0 = bias[gc], b1 = bias[gc + 1];
            float c00 = C[mt * 2 + nt][0] + b0, c01 = C[mt * 2 + nt][1] + b1;
            float c10 = C[mt * 2 + nt][2] + b0, c11 = C[mt * 2 + nt][3] + b1;
            if (dorelu) {
                c00 = fmaxf(c00, 0.f); c01 = fmaxf(c01, 0.f);
                c10 = fmaxf(c10, 0.f); c11 = fmaxf(c11, 0.f);
            }
            if (r0 < N_NODES)
                *(float2*)(OP + (size_t)r0 * 64 + gc) = make_float2(c00, c01);
            if (r1 < N_NODES)
                *(float2*)(OP + (size_t)r1 * 64 + gc) = make_float2(c10, c11);
        }
    }
}

// ---------------- launch ----------------
extern "C" void kernel_launch(void* const* d_in, const int* in_sizes, int n_in,
                              void* d_out, int out_size) {
    const int* feat = (const int*)d_in[0];
    const int* src = (const int*)d_in[1];
    const int* dst = (const int*)d_in[2];
    const int* etype = (const int*)d_in[3];
    const float* norm = (const float*)d_in[4];
    const float* emb = (const float*)d_in[5];
    const float* smw = (const float*)d_in[6];
    const float* smb = (const float*)d_in[7];
    const float* V1 = (const float*)d_in[8];
    const float* c1 = (const float*)d_in[9];
    const float* b1 = (const float*)d_in[10];
    const float* V2 = (const float*)d_in[11];
    const float* c2 = (const float*)d_in[12];
    const float* b2 = (const float*)d_in[13];
    float* out = (float*)d_out;

    const int smemSM = (128 * NLDA * 2 + 64 * NLDA * 2) * 2 + 128 * 8 * 4;
    const int smemFU = (128 * NLDA * 2 + 64 * NLDA * 2) * 2;       // 55296
    static int attr_done = 0;
    if (!attr_done) {
        cudaFuncSetAttribute(k_sm, cudaFuncAttributeMaxDynamicSharedMemorySize, smemSM);
        cudaFuncSetAttribute(k_fused, cudaFuncAttributeMaxDynamicSharedMemorySize, smemFU);
        attr_done = 1;
    }

    // CSR build over (dst, rel) segments
    k_zero_cnt<<<(NSEG + 255) / 256, 256>>>();
    k_hist<<<N_EDGES / 256, 256>>>(dst, etype);
    k_scan_local<<<SCAN_BLOCKS, 1024>>>();
    k_scan_bsums<<<1, 1024>>>(SCAN_BLOCKS);
    k_scan_add<<<SCAN_BLOCKS, 1024>>>();
    k_scatter<<<N_EDGES / 256, 256>>>(src, dst, etype, norm);

    // weights (bf16 hi/lo, transposed)
    k_prepw<<<(2 * H_DIM * K_TOT) / 256, 256>>>(V1, c1, V2, c2);

    // size matcher -> g_x
    k_sm<<<(N_NODES + 127) / 128, 256, smemSM>>>(feat, emb, smw, smb);

    // fused layers
    k_fused<<<(N_NODES + 127) / 128, 256, smemFU>>>(0, b1, nullptr);
    k_fused<<<(N_NODES + 127) / 128, 256, smemFU>>>(1, b2, out);
}

// round 5
// speedup vs baseline: 1.4757x; 1.1293x over previous
#include <cuda_runtime.h>
#include <cuda_bf16.h>
#include <stdint.h>

#define N_NODES 100000
#define N_EDGES 1600000
#define NUM_RELS 8
#define H_DIM 64
#define K_TOT 512             // NUM_RELS * H_DIM
#define NSEG (N_NODES * NUM_RELS)      // 800000 segments (dst*8+etype)
#define SCAN_BLOCKS ((NSEG + 1023) / 1024)   // 782
#define NLDA 72               // padded smem leading dim (bf16 elems)
#define EDGE_CAP 2944         // smem edge-staging capacity per 128-node block

// ---------------- scratch (static device allocations) ----------------
__device__ float g_x[(size_t)N_NODES * H_DIM];          // 25.6 MB
__device__ float g_h[(size_t)N_NODES * H_DIM];          // 25.6 MB
__device__ int   g_cnt[NSEG];
__device__ int   g_rowptr[NSEG + 1];
__device__ int   g_wp[NSEG];
__device__ int   g_bsum[1024];
__device__ int   g_esrc[N_EDGES];
__device__ float g_enorm[N_EDGES];
__device__ __nv_bfloat16 g_Wth[2 * H_DIM * K_TOT];      // Bt layout [layer][o*512 + r*64+k] hi
__device__ __nv_bfloat16 g_Wtl[2 * H_DIM * K_TOT];      // lo

// ---------------- CSR build over (dst, rel) segments ----------------
__global__ void k_zero_cnt() {
    int i = blockIdx.x * blockDim.x + threadIdx.x;
    if (i < NSEG) g_cnt[i] = 0;
}

__global__ void k_hist(const int* __restrict__ dst, const int* __restrict__ etype) {
    int e = blockIdx.x * blockDim.x + threadIdx.x;
    if (e < N_EDGES) atomicAdd(&g_cnt[dst[e] * NUM_RELS + etype[e]], 1);
}

__global__ void k_scan_local() {   // 1024 threads/block
    __shared__ int warpsums[32];
    int i = blockIdx.x * 1024 + threadIdx.x;
    int v = (i < NSEG) ? g_cnt[i] : 0;
    int lane = threadIdx.x & 31, wid = threadIdx.x >> 5;
    int s = v;
    #pragma unroll
    for (int d = 1; d < 32; d <<= 1) {
        int t = __shfl_up_sync(0xFFFFFFFFu, s, d);
        if (lane >= d) s += t;
    }
    if (lane == 31) warpsums[wid] = s;
    __syncthreads();
    if (wid == 0) {
        int ws = warpsums[lane];
        #pragma unroll
        for (int d = 1; d < 32; d <<= 1) {
            int t = __shfl_up_sync(0xFFFFFFFFu, ws, d);
            if (lane >= d) ws += t;
        }
        warpsums[lane] = ws;
    }
    __syncthreads();
    int base = (wid > 0) ? warpsums[wid - 1] : 0;
    int incl = s + base;
    if (i < NSEG) g_rowptr[i] = incl - v;               // local exclusive
    if (threadIdx.x == 1023) g_bsum[blockIdx.x] = incl; // block total
}

__global__ void k_scan_bsums(int nb) {   // 1 block of 1024
    __shared__ int sh[1024];
    int t = threadIdx.x;
    int v = (t < nb) ? g_bsum[t] : 0;
    sh[t] = v;
    __syncthreads();
    for (int off = 1; off < 1024; off <<= 1) {
        int add = (t >= off) ? sh[t - off] : 0;
        __syncthreads();
        sh[t] += add;
        __syncthreads();
    }
    if (t < nb) g_bsum[t] = sh[t] - v;   // exclusive
}

__global__ void k_scan_add() {
    int i = blockIdx.x * 1024 + threadIdx.x;
    if (i < NSEG) {
        int val = g_rowptr[i] + g_bsum[blockIdx.x];
        g_rowptr[i] = val;
        g_wp[i] = val;
    }
    if (blockIdx.x == 0 && threadIdx.x == 0) g_rowptr[NSEG] = N_EDGES;
}

__global__ void k_scatter(const int* __restrict__ src, const int* __restrict__ dst,
                          const int* __restrict__ etype, const float* __restrict__ norm) {
    int e = blockIdx.x * blockDim.x + threadIdx.x;
    if (e >= N_EDGES) return;
    int seg = dst[e] * NUM_RELS + etype[e];
    int p = atomicAdd(&g_wp[seg], 1);
    g_esrc[p] = src[e];
    g_enorm[p] = norm[e];
}

// ---------------- weight prep -> transposed bf16 hi/lo ----------------
__global__ void k_prepw(const float* __restrict__ V1, const float* __restrict__ c1,
                        const float* __restrict__ V2, const float* __restrict__ c2) {
    int t = blockIdx.x * blockDim.x + threadIdx.x;
    if (t >= 2 * H_DIM * K_TOT) return;
    int sel = t >= H_DIM * K_TOT;
    int u = t & (H_DIM * K_TOT - 1);
    int o = u >> 9;          // 0..63
    int c = u & 511;         // r*64+k
    int r = c >> 6, k = c & 63;
    const float* V = sel ? V2 : V1;
    const float* cp = sel ? c2 : c1;
    float s = 0.f;
    #pragma unroll
    for (int b = 0; b < 8; b++)
        s += cp[r * 8 + b] * V[(b * 64 + k) * 64 + o];
    __nv_bfloat16 hi = __float2bfloat16(s);
    __nv_bfloat16 lo = __float2bfloat16(s - __bfloat162float(hi));
    g_Wth[t] = hi;
    g_Wtl[t] = lo;
}

// ---------------- mma helper ----------------
__device__ __forceinline__ void mma16816(float* c, const uint32_t* a, const uint32_t* b) {
    asm volatile(
        "mma.sync.aligned.m16n8k16.row.col.f32.bf16.bf16.f32 "
        "{%0,%1,%2,%3}, {%4,%5,%6,%7}, {%8,%9}, {%0,%1,%2,%3};\n"
        : "+f"(c[0]), "+f"(c[1]), "+f"(c[2]), "+f"(c[3])
        : "r"(a[0]), "r"(a[1]), "r"(a[2]), "r"(a[3]), "r"(b[0]), "r"(b[1]));
}

__device__ __forceinline__ void split_bf16(float v, __nv_bfloat16& hi, __nv_bfloat16& lo) {
    hi = __float2bfloat16(v);
    lo = __float2bfloat16(v - __bfloat162float(hi));
}

// ---------------- size matcher: g_x = gather(emb)[N,256] @ sm_w^T + sm_b -----------
__global__ void k_sm(const int* __restrict__ feat, const float* __restrict__ emb,
                     const float* __restrict__ smw, const float* __restrict__ smb) {
    extern __shared__ char smraw[];
    __nv_bfloat16* Ahi = (__nv_bfloat16*)smraw;                 // 128*72
    __nv_bfloat16* Alo = Ahi + 128 * NLDA;
    __nv_bfloat16* Bhi = Alo + 128 * NLDA;                      // 64*72
    __nv_bfloat16* Blo = Bhi + 64 * NLDA;
    int* sfeat = (int*)(Blo + 64 * NLDA);                       // 128*8

    int tid = threadIdx.x;
    int rb = blockIdx.x * 128;

    for (int idx = tid; idx < 128 * 8; idx += 256) {
        int r = idx >> 3, j = idx & 7;
        sfeat[idx] = (rb + r < N_NODES) ? feat[(size_t)(rb + r) * 8 + j] : 0;
    }

    int lane = tid & 31, warp = tid >> 5;
    int wr = (warp >> 2) * 64;       // 0 or 64
    int wc = (warp & 3) * 16;        // 0,16,32,48
    int g = lane >> 2, t = lane & 3;

    float C[8][4];
    #pragma unroll
    for (int i = 0; i < 8; i++)
        #pragma unroll
        for (int j = 0; j < 4; j++) C[i][j] = 0.f;

    for (int kc = 0; kc < 4; kc++) {
        __syncthreads();
        for (int idx = tid; idx < 128 * 64; idx += 256) {
            int r = idx >> 6, k = idx & 63;
            float v = 0.f;
            if (rb + r < N_NODES) {
                int fid = sfeat[r * 8 + kc * 2 + (k >> 5)];
                v = emb[(size_t)fid * 32 + (k & 31)];
            }
            __nv_bfloat16 h, l; split_bf16(v, h, l);
            Ahi[r * NLDA + k] = h; Alo[r * NLDA + k] = l;
        }
        for (int idx = tid; idx < 64 * 64; idx += 256) {
            int n = idx >> 6, k = idx & 63;
            float v = smw[n * 256 + kc * 64 + k];
            __nv_bfloat16 h, l; split_bf16(v, h, l);
            Bhi[n * NLDA + k] = h; Blo[n * NLDA + k] = l;
        }
        __syncthreads();

        #pragma unroll
        for (int ks = 0; ks < 4; ks++) {
            int k0 = ks * 16;
            #pragma unroll
            for (int p = 0; p < 3; p++) {
                const __nv_bfloat16* As = (p == 1) ? Alo : Ahi;
                const __nv_bfloat16* Bs = (p == 2) ? Blo : Bhi;
                uint32_t a[4][4], b[2][2];
                #pragma unroll
                for (int mt = 0; mt < 4; mt++) {
                    int r0 = wr + mt * 16;
                    a[mt][0] = *(const uint32_t*)(As + (r0 + g) * NLDA + k0 + 2 * t);
                    a[mt][1] = *(const uint32_t*)(As + (r0 + g + 8) * NLDA + k0 + 2 * t);
                    a[mt][2] = *(const uint32_t*)(As + (r0 + g) * NLDA + k0 + 8 + 2 * t);
                    a[mt][3] = *(const uint32_t*)(As + (r0 + g + 8) * NLDA + k0 + 8 + 2 * t);
                }
                #pragma unroll
                for (int nt = 0; nt < 2; nt++) {
                    int c0 = wc + nt * 8 + g;
                    b[nt][0] = *(const uint32_t*)(Bs + c0 * NLDA + k0 + 2 * t);
                    b[nt][1] = *(const uint32_t*)(Bs + c0 * NLDA + k0 + 8 + 2 * t);
                }
                #pragma unroll
                for (int mt = 0; mt < 4; mt++)
                    #pragma unroll
                    for (int nt = 0; nt < 2; nt++)
                        mma16816(C[mt * 2 + nt], a[mt], b[nt]);
            }
        }
    }

    #pragma unroll
    for (int mt = 0; mt < 4; mt++) {
        int r0 = rb + wr + mt * 16 + g;
        int r1 = r0 + 8;
        #pragma unroll
        for (int nt = 0; nt < 2; nt++) {
            int gc = wc + nt * 8 + 2 * t;
            float b0 = smb[gc], b1 = smb[gc + 1];
            if (r0 < N_NODES)
                *(float2*)(g_x + (size_t)r0 * 64 + gc) =
                    make_float2(C[mt * 2 + nt][0] + b0, C[mt * 2 + nt][1] + b1);
            if (r1 < N_NODES)
                *(float2*)(g_x + (size_t)r1 * 64 + gc) =
                    make_float2(C[mt * 2 + nt][2] + b0, C[mt * 2 + nt][3] + b1);
        }
    }
}

// ---------------- fused layer v2: smem-staged metadata, 512 threads ----------------
// block = 128 nodes, 16 warps. Warp w aggregates nodes w*8..w*8+7 per rel chunk,
// then all warps cooperate in the 128x64 MMA (warp tile 32x16).
__global__ __launch_bounds__(512, 2)
void k_fused(int phase, const float* __restrict__ bias, float* __restrict__ dout) {
    const float* __restrict__ X = phase ? g_h : g_x;
    float* __restrict__ OP = phase ? dout : g_h;
    const __nv_bfloat16* __restrict__ Wh = g_Wth + phase * H_DIM * K_TOT;
    const __nv_bfloat16* __restrict__ Wl = g_Wtl + phase * H_DIM * K_TOT;

    extern __shared__ char smraw[];
    __nv_bfloat16* Ahi = (__nv_bfloat16*)smraw;             // 128*72 bf16
    __nv_bfloat16* Alo = Ahi + 128 * NLDA;
    __nv_bfloat16* Bhi = Alo + 128 * NLDA;                  // 64*72
    __nv_bfloat16* Blo = Bhi + 64 * NLDA;
    int*   rps = (int*)(Blo + 64 * NLDA);                   // 1025 (+3 pad)
    int*   ssrc = rps + 1028;                               // EDGE_CAP
    float* snrm = (float*)(ssrc + EDGE_CAP);                // EDGE_CAP

    int tid = threadIdx.x;
    int rb = blockIdx.x * 128;
    int lane = tid & 31, warp = tid >> 5;
    int c = lane * 2;

    // ---- stage rowptr slice ----
    for (int idx = tid; idx < 1025; idx += 512) {
        int gi = rb * NUM_RELS + idx;
        rps[idx] = g_rowptr[gi < NSEG ? gi : NSEG];
    }
    __syncthreads();
    int ebase = rps[0];
    int ecnt = rps[1024] - ebase;
    bool fits = (ecnt <= EDGE_CAP);

    // ---- stage edge metadata (coalesced) ----
    if (fits) {
        for (int idx = tid; idx < ecnt; idx += 512) {
            ssrc[idx] = g_esrc[ebase + idx];
            snrm[idx] = g_enorm[ebase + idx];
        }
    }
    __syncthreads();
    const int*   ep = fits ? (const int*)ssrc : (const int*)(g_esrc + ebase);
    const float* np = fits ? (const float*)snrm : (const float*)(g_enorm + ebase);

    int wr = (warp >> 2) * 32;        // MMA row group (0,32,64,96)
    int wc = (warp & 3) * 16;         // MMA col group (0,16,32,48)
    int g = lane >> 2, t = lane & 3;

    float C[4][4];
    #pragma unroll
    for (int i = 0; i < 4; i++)
        #pragma unroll
        for (int j = 0; j < 4; j++) C[i][j] = 0.f;

    for (int r = 0; r < NUM_RELS; r++) {
        if (r) __syncthreads();   // previous chunk's MMA reads done

        // --- aggregate 8 nodes into smem chunk rows ---
        int ln0 = warp * 8;
        #pragma unroll 1
        for (int i = 0; i < 8; i++) {
            int row = ln0 + i;
            int e   = rps[row * NUM_RELS + r] - ebase;
            int end = rps[row * NUM_RELS + r + 1] - ebase;
            float ax = 0.f, ay = 0.f;
            for (; e + 4 <= end; e += 4) {
                int s0 = ep[e],     s1 = ep[e + 1];
                int s2 = ep[e + 2], s3 = ep[e + 3];
                float n0 = np[e],     n1 = np[e + 1];
                float n2 = np[e + 2], n3 = np[e + 3];
                float2 v0 = *(const float2*)(X + (size_t)s0 * 64 + c);
                float2 v1 = *(const float2*)(X + (size_t)s1 * 64 + c);
                float2 v2 = *(const float2*)(X + (size_t)s2 * 64 + c);
                float2 v3 = *(const float2*)(X + (size_t)s3 * 64 + c);
                ax = fmaf(n0, v0.x, ax); ay = fmaf(n0, v0.y, ay);
                ax = fmaf(n1, v1.x, ax); ay = fmaf(n1, v1.y, ay);
                ax = fmaf(n2, v2.x, ax); ay = fmaf(n2, v2.y, ay);
                ax = fmaf(n3, v3.x, ax); ay = fmaf(n3, v3.y, ay);
            }
            if (e < end) {
                // up to 3 remaining; issue all independently
                int s0 = ep[e];
                float n0 = np[e];
                int s1 = (e + 1 < end) ? ep[e + 1] : s0;
                float n1 = (e + 1 < end) ? np[e + 1] : 0.f;
                int s2 = (e + 2 < end) ? ep[e + 2] : s0;
                float n2 = (e + 2 < end) ? np[e + 2] : 0.f;
                float2 v0 = *(const float2*)(X + (size_t)s0 * 64 + c);
                float2 v1 = *(const float2*)(X + (size_t)s1 * 64 + c);
                float2 v2 = *(const float2*)(X + (size_t)s2 * 64 + c);
                ax = fmaf(n0, v0.x, ax); ay = fmaf(n0, v0.y, ay);
                ax = fmaf(n1, v1.x, ax); ay = fmaf(n1, v1.y, ay);
                ax = fmaf(n2, v2.x, ax); ay = fmaf(n2, v2.y, ay);
            }
            __nv_bfloat16 h0, l0, h1, l1;
            split_bf16(ax, h0, l0);
            split_bf16(ay, h1, l1);
            __nv_bfloat162 ph; ph.x = h0; ph.y = h1;
            __nv_bfloat162 pl; pl.x = l0; pl.y = l1;
            *(__nv_bfloat162*)(Ahi + row * NLDA + c) = ph;
            *(__nv_bfloat162*)(Alo + row * NLDA + c) = pl;
        }

        // --- load B chunk (W rows for this relation), L2-resident ---
        for (int idx = tid; idx < 64 * 64; idx += 512) {
            int n = idx >> 6, k = idx & 63;
            Bhi[n * NLDA + k] = Wh[n * K_TOT + r * 64 + k];
            Blo[n * NLDA + k] = Wl[n * K_TOT + r * 64 + k];
        }
        __syncthreads();

        // --- 3-pass MMA over this 64-wide K chunk (warp tile 32x16) ---
        #pragma unroll
        for (int ks = 0; ks < 4; ks++) {
            int k0 = ks * 16;
            #pragma unroll
            for (int p = 0; p < 3; p++) {
                const __nv_bfloat16* As = (p == 1) ? Alo : Ahi;
                const __nv_bfloat16* Bs = (p == 2) ? Blo : Bhi;
                uint32_t a[2][4], b[2][2];
                #pragma unroll
                for (int mt = 0; mt < 2; mt++) {
                    int r0 = wr + mt * 16;
                    a[mt][0] = *(const uint32_t*)(As + (r0 + g) * NLDA + k0 + 2 * t);
                    a[mt][1] = *(const uint32_t*)(As + (r0 + g + 8) * NLDA + k0 + 2 * t);
                    a[mt][2] = *(const uint32_t*)(As + (r0 + g) * NLDA + k0 + 8 + 2 * t);
                    a[mt][3] = *(const uint32_t*)(As + (r0 + g + 8) * NLDA + k0 + 8 + 2 * t);
                }
                #pragma unroll
                for (int nt = 0; nt < 2; nt++) {
                    int c0 = wc + nt * 8 + g;
                    b[nt][0] = *(const uint32_t*)(Bs + c0 * NLDA + k0 + 2 * t);
                    b[nt][1] = *(const uint32_t*)(Bs + c0 * NLDA + k0 + 8 + 2 * t);
                }
                #pragma unroll
                for (int mt = 0; mt < 2; mt++)
                    #pragma unroll
                    for (int nt = 0; nt < 2; nt++)
                        mma16816(C[mt * 2 + nt], a[mt], b[nt]);
            }
        }
    }

    // --- epilogue: bias (+relu for layer 1) ---
    int dorelu = (phase == 0);
    #pragma unroll
    for (int mt = 0; mt < 2; mt++) {
        int r0 = rb + wr + mt * 16 + g;
        int r1 = r0 + 8;
        #pragma unroll
        for (int nt = 0; nt < 2; nt++) {
            int gc = wc + nt * 8 + 2 * t;
            float b0 = bias[gc], b1 = bias[gc + 1];
            float c00 = C[mt * 2 + nt][0] + b0, c01 = C[mt * 2 + nt][1] + b1;
            float c10 = C[mt * 2 + nt][2] + b0, c11 = C[mt * 2 + nt][3] + b1;
            if (dorelu) {
                c00 = fmaxf(c00, 0.f); c01 = fmaxf(c01, 0.f);
                c10 = fmaxf(c10, 0.f); c11 = fmaxf(c11, 0.f);
            }
            if (r0 < N_NODES)
                *(float2*)(OP + (size_t)r0 * 64 + gc) = make_float2(c00, c01);
            if (r1 < N_NODES)
                *(float2*)(OP + (size_t)r1 * 64 + gc) = make_float2(c10, c11);
        }
    }
}

// ---------------- launch ----------------
extern "C" void kernel_launch(void* const* d_in, const int* in_sizes, int n_in,
                              void* d_out, int out_size) {
    const int* feat = (const int*)d_in[0];
    const int* src = (const int*)d_in[1];
    const int* dst = (const int*)d_in[2];
    const int* etype = (const int*)d_in[3];
    const float* norm = (const float*)d_in[4];
    const float* emb = (const float*)d_in[5];
    const float* smw = (const float*)d_in[6];
    const float* smb = (const float*)d_in[7];
    const float* V1 = (const float*)d_in[8];
    const float* c1 = (const float*)d_in[9];
    const float* b1 = (const float*)d_in[10];
    const float* V2 = (const float*)d_in[11];
    const float* c2 = (const float*)d_in[12];
    const float* b2 = (const float*)d_in[13];
    float* out = (float*)d_out;

    const int smemSM = (128 * NLDA * 2 + 64 * NLDA * 2) * 2 + 128 * 8 * 4;
    const int smemFU = (128 * NLDA * 2 + 64 * NLDA * 2) * 2   // A+B hi/lo  (55296)
                     + 1028 * 4                                // rowptr slice
                     + EDGE_CAP * 8;                           // edge meta
    static int attr_done = 0;
    if (!attr_done) {
        cudaFuncSetAttribute(k_sm, cudaFuncAttributeMaxDynamicSharedMemorySize, smemSM);
        cudaFuncSetAttribute(k_fused, cudaFuncAttributeMaxDynamicSharedMemorySize, smemFU);
        attr_done = 1;
    }

    // CSR build over (dst, rel) segments
    k_zero_cnt<<<(NSEG + 255) / 256, 256>>>();
    k_hist<<<N_EDGES / 256, 256>>>(dst, etype);
    k_scan_local<<<SCAN_BLOCKS, 1024>>>();
    k_scan_bsums<<<1, 1024>>>(SCAN_BLOCKS);
    k_scan_add<<<SCAN_BLOCKS, 1024>>>();
    k_scatter<<<N_EDGES / 256, 256>>>(src, dst, etype, norm);

    // weights (bf16 hi/lo, transposed)
    k_prepw<<<(2 * H_DIM * K_TOT) / 256, 256>>>(V1, c1, V2, c2);

    // size matcher -> g_x
    k_sm<<<(N_NODES + 127) / 128, 256, smemSM>>>(feat, emb, smw, smb);

    // fused layers
    k_fused<<<(N_NODES + 127) / 128, 512, smemFU>>>(0, b1, nullptr);
    k_fused<<<(N_NODES + 127) / 128, 512, smemFU>>>(1, b2, out);
}